// round 8
// baseline (speedup 1.0000x reference)
#include <cuda_runtime.h>

#define B_VOX   256
#define NPC     40
#define NE      32
#define ORD     8                    // EPG orders per lane
#define LPC     4                    // lanes per compartment (32 orders)
#define CPW     8                    // compartments per warp
#define WARPS   (NPC / CPW)          // 5
#define THREADS (WARPS * 32)         // 160

// y-form EPG: y_{k+1} = S^2 · M · y_k  (y = S·x, E = S·M·S, M = D·T·D blockdiag)
// sub-lane s = lane&3 holds orders 8s+1..8s+8 as F[8],G[8],u[8] (u = C·Z);
// compartment = wz*8 + (lane>>2); x0 lives on sub-lane 0.
// M per order:  mF = A·F + B·G + u ;  mG = B·F + A·G - u
//               u' = CD·(G - F) + Ez·u  (CD = C·Dz) ;  mx0 = e2²·x0
// S² (F down 2 orders, G up 2 orders):
//   F[0] <- prev-lane mF[6]   (s=0: mG[0])
//   F[1] <- prev-lane mF[7]   (s=0: mx0)
//   F[j] <- mF[j-2], j=2..7
//   G[j] <- mG[j+2], j=0..5
//   G[6] <- next-lane mG[0]   (s=3: 0)
//   G[7] <- next-lane mG[1]   (s=3: 0)
//   x0 <- mG[1] (s=0);  echo_k = s=0 mG[0]
// Init y0 = S·x0: x0 = cos(a/2), F_1 = sin(a/2), rest 0.

__global__ __launch_bounds__(THREADS) void epg_kernel(
    const float* __restrict__ refoc,    // (256,)
    const float* __restrict__ t2s,      // (256, 40)
    const float* __restrict__ wts,      // (256, 40)
    float* __restrict__ out)            // (256, 32)
{
    const int b    = blockIdx.x;
    const int lane = threadIdx.x & 31;
    const int wz   = threadIdx.x >> 5;
    const int s    = lane & (LPC - 1);
    const int grp  = lane >> 2;
    const bool sLo = (s == 0);
    const bool sHi = (s == LPC - 1);
    const unsigned FULL = 0xFFFFFFFFu;

    __shared__ float smem[NPC][NE + 1];      // +1 pad: conflict-free leader STS

    // per-voxel rotation constants (one sincos + half-angle identities)
    const float a  = refoc[b] * 0.017453292519943295f;
    float sa, ca;
    sincosf(a, &sa, &ca);
    const float c2 = 0.5f * (1.0f + ca);     // cos^2(a/2)
    const float s2 = 0.5f * (1.0f - ca);     // sin^2(a/2)
    const float ch = sqrtf(c2);              // a/2 in (60°,90°] -> cos >= 0
    const float sh = sqrtf(s2);
    const float e1   = 0.99501247919268231f; // exp(-5/1000)
    const float e1sq = e1 * e1;

    // per-compartment fused coefficients
    const int   c    = wz * CPW + grp;
    const float e2   = expf(-5.0f / t2s[b * NPC + c]);
    const float e2sq = e2 * e2;
    const float A    = c2 * e2sq;
    const float Bc   = s2 * e2sq;
    const float Cc   = sa * e2 * e1;
    const float Dz   = 0.5f * sa * e1 * e2;
    const float Ez   = ca * e1sq;
    const float CD   = Cc * Dz;              // u-recurrence coefficient
    const float w    = wts[b * NPC + c];

    // init y0 = S·x0
    float F[ORD], G[ORD], u[ORD];
    #pragma unroll
    for (int j = 0; j < ORD; ++j) { F[j] = 0.f; G[j] = 0.f; u[j] = 0.f; }
    if (sLo) F[0] = sh;
    float x0 = ch;                           // meaningful on sub-lane 0

    #pragma unroll 4
    for (int k = 0; k < NE; ++k) {
        // ---- M = D·T·D (all local, u = C·Z form) ----
        float mF[ORD], mG[ORD];
        #pragma unroll
        for (int j = 0; j < ORD; ++j) {
            mF[j] = fmaf(A,  F[j], fmaf(Bc, G[j],  u[j]));
            mG[j] = fmaf(Bc, F[j], fmaf(A,  G[j], -u[j]));
            u[j]  = fmaf(CD, G[j], fmaf(-CD, F[j], Ez * u[j]));
        }
        const float mx0 = e2sq * x0;

        // ---- S²: one shuffle segment, 4 shfls serve all 8 compartments ----
        const float cF0 = __shfl_up_sync  (FULL, mF[ORD-2], 1, LPC);
        const float cF1 = __shfl_up_sync  (FULL, mF[ORD-1], 1, LPC);
        const float cG0 = __shfl_down_sync(FULL, mG[0],     1, LPC);
        const float cG1 = __shfl_down_sync(FULL, mG[1],     1, LPC);

        if (sLo) smem[c][k] = w * mG[0];     // echo_k (sub-lane-0 local)

        F[0] = sLo ? mG[0] : cF0;
        F[1] = sLo ? mx0   : cF1;
        #pragma unroll
        for (int j = 2; j < ORD; ++j) F[j] = mF[j - 2];
        #pragma unroll
        for (int j = 0; j < ORD - 2; ++j) G[j] = mG[j + 2];
        G[ORD-2] = sHi ? 0.f : cG0;
        G[ORD-1] = sHi ? 0.f : cG1;
        x0 = mG[1];                          // new x0 (valid on sub-lane 0)
    }

    __syncthreads();

    // warp 0: sum 40 compartments per echo, normalize by echo 0
    if (threadIdx.x < 32) {
        float acc = 0.0f;
        #pragma unroll
        for (int r = 0; r < NPC; ++r) acc += smem[r][lane];
        const float acc0 = __shfl_sync(FULL, acc, 0);
        out[b * NE + lane] = acc / acc0;
    }
}

extern "C" void kernel_launch(void* const* d_in, const int* in_sizes, int n_in,
                              void* d_out, int out_size) {
    const float* refoc = (const float*)d_in[0];
    const float* t2s   = (const float*)d_in[1];
    const float* wts   = (const float*)d_in[2];
    float* out = (float*)d_out;
    epg_kernel<<<B_VOX, THREADS>>>(refoc, t2s, wts, out);
}